// round 10
// baseline (speedup 1.0000x reference)
#include <cuda_runtime.h>
#include <stdint.h>

#define OUTPUT_DIM 64
#define NB_CTRL_SIG 16
#define FULL_ROW_BYTES (OUTPUT_DIM * NB_CTRL_SIG * 4)  // 4096 B per input row
#define BLOCK_BYTES (OUTPUT_DIM * 4)                   // 256 B selected block
#define VEC_BYTES 32                                   // 256-bit per slot
#define SLOTS_PER_ROW (BLOCK_BYTES / VEC_BYTES)        // 8
#define UNROLL 4

// L2 budget (126 MB): pin output (64 MB) + indices (1 MB) + reads of rows
// b < B_PIN (13/16 of batch -> 52 MB). Remaining 3/16 of reads (12 MB) are
// explicitly streamed (evict_first) so they never victimize pinned lines.
// This breaks the cyclic-LRU thrash that made ALL 65 MB of reads miss in R9.
__device__ __forceinline__ void ld_v8_evict_last(const void* p, uint32_t r[8]) {
    asm volatile("ld.global.nc.L2::evict_last.v8.b32 {%0,%1,%2,%3,%4,%5,%6,%7}, [%8];"
                 : "=r"(r[0]), "=r"(r[1]), "=r"(r[2]), "=r"(r[3]),
                   "=r"(r[4]), "=r"(r[5]), "=r"(r[6]), "=r"(r[7])
                 : "l"(p));
}
__device__ __forceinline__ void ld_v8_evict_first(const void* p, uint32_t r[8]) {
    asm volatile("ld.global.nc.L2::evict_first.v8.b32 {%0,%1,%2,%3,%4,%5,%6,%7}, [%8];"
                 : "=r"(r[0]), "=r"(r[1]), "=r"(r[2]), "=r"(r[3]),
                   "=r"(r[4]), "=r"(r[5]), "=r"(r[6]), "=r"(r[7])
                 : "l"(p));
}
__device__ __forceinline__ void st_v8_evict_last(void* p, const uint32_t r[8]) {
    asm volatile("st.global.L2::evict_last.v8.b32 [%0], {%1,%2,%3,%4,%5,%6,%7,%8};"
                 :: "l"(p),
                    "r"(r[0]), "r"(r[1]), "r"(r[2]), "r"(r[3]),
                    "r"(r[4]), "r"(r[5]), "r"(r[6]), "r"(r[7])
                 : "memory");
}

// out[b, 0:64] = full_input[b, idx[b]*64 : idx[b]*64+64]
__global__ void multiplexer_kernel(const char* __restrict__ full_input,
                                   const int* __restrict__ indices,
                                   char* __restrict__ out,
                                   int total_slots, int stride_slots,
                                   int pin_slot_limit /* slots with b < B_PIN */) {
    int s0 = blockIdx.x * blockDim.x + threadIdx.x;

    int s1 = s0 + stride_slots;
    int s2 = s1 + stride_slots;
    int s3 = s2 + stride_slots;

    if (s3 < total_slots) {
        int b0 = s0 >> 3, j0 = s0 & 7;
        int b1 = s1 >> 3, j1 = s1 & 7;
        int b2 = s2 >> 3, j2 = s2 & 7;
        int b3 = s3 >> 3, j3 = s3 & 7;

        int i0 = __ldg(&indices[b0]);
        int i1 = __ldg(&indices[b1]);
        int i2 = __ldg(&indices[b2]);
        int i3 = __ldg(&indices[b3]);

        const char* p0 = full_input + (size_t)b0 * FULL_ROW_BYTES + i0 * BLOCK_BYTES + j0 * VEC_BYTES;
        const char* p1 = full_input + (size_t)b1 * FULL_ROW_BYTES + i1 * BLOCK_BYTES + j1 * VEC_BYTES;
        const char* p2 = full_input + (size_t)b2 * FULL_ROW_BYTES + i2 * BLOCK_BYTES + j2 * VEC_BYTES;
        const char* p3 = full_input + (size_t)b3 * FULL_ROW_BYTES + i3 * BLOCK_BYTES + j3 * VEC_BYTES;

        uint32_t v0[8], v1[8], v2[8], v3[8];
        // branch is warp-uniform except at the single partition boundary
        if (s0 < pin_slot_limit) ld_v8_evict_last(p0, v0); else ld_v8_evict_first(p0, v0);
        if (s1 < pin_slot_limit) ld_v8_evict_last(p1, v1); else ld_v8_evict_first(p1, v1);
        if (s2 < pin_slot_limit) ld_v8_evict_last(p2, v2); else ld_v8_evict_first(p2, v2);
        if (s3 < pin_slot_limit) ld_v8_evict_last(p3, v3); else ld_v8_evict_first(p3, v3);

        st_v8_evict_last(out + (size_t)s0 * VEC_BYTES, v0);
        st_v8_evict_last(out + (size_t)s1 * VEC_BYTES, v1);
        st_v8_evict_last(out + (size_t)s2 * VEC_BYTES, v2);
        st_v8_evict_last(out + (size_t)s3 * VEC_BYTES, v3);
    } else {
        #pragma unroll
        for (int u = 0; u < UNROLL; u++) {
            int s = s0 + u * stride_slots;
            if (s < total_slots) {
                int b = s >> 3, j = s & 7;
                int i = __ldg(&indices[b]);
                const char* p = full_input + (size_t)b * FULL_ROW_BYTES + i * BLOCK_BYTES + j * VEC_BYTES;
                uint32_t v[8];
                if (s < pin_slot_limit) ld_v8_evict_last(p, v); else ld_v8_evict_first(p, v);
                st_v8_evict_last(out + (size_t)s * VEC_BYTES, v);
            }
        }
    }
}

extern "C" void kernel_launch(void* const* d_in, const int* in_sizes, int n_in,
                              void* d_out, int out_size) {
    const char* full_input = (const char*)d_in[0];
    const int*  indices    = (const int*)d_in[1];
    char*       out        = (char*)d_out;

    int batch       = in_sizes[1];                  // 262144
    int total_slots = batch * SLOTS_PER_ROW;        // 2,097,152 slots (32 B each)

    // Pin reads for rows b < 13/16 of batch (52 MB of selected blocks).
    // Slots are row-major (slot = b*8 + j), so slot threshold = B_PIN * 8.
    int b_pin          = (batch / 16) * 13;         // 212,992 rows
    int pin_slot_limit = b_pin * SLOTS_PER_ROW;

    int block   = 256;
    int threads = (total_slots + UNROLL - 1) / UNROLL;  // 524,288
    int grid    = (threads + block - 1) / block;        // 2048
    int stride  = grid * block;

    multiplexer_kernel<<<grid, block>>>(full_input, indices, out,
                                        total_slots, stride, pin_slot_limit);
}

// round 11
// speedup vs baseline: 1.1237x; 1.1237x over previous
#include <cuda_runtime.h>
#include <stdint.h>

#define OUTPUT_DIM 64
#define NB_CTRL_SIG 16
#define FULL_ROW_BYTES (OUTPUT_DIM * NB_CTRL_SIG * 4)  // 4096 B per input row
#define BLOCK_BYTES (OUTPUT_DIM * 4)                   // 256 B selected block
#define VEC_BYTES 32                                   // 256-bit per slot
#define SLOTS_PER_ROW (BLOCK_BYTES / VEC_BYTES)        // 8
#define UNROLL 4
#define ROWS_PER_WARP_LEG 4                            // 32 lanes / 8 slots-per-row

// R9 polarity (proven best):
//  - stores: L2::evict_last -> dense 64 MB output stays dirty-resident in L2
//    across graph replays (writebacks only at the end).
//  - input reads: L2::evict_first -> use-once sparse stream, never displaces
//    the pinned output.
//  - indices: one LDG per row per warp (shuffle-broadcast), L2-resident.
__device__ __forceinline__ void ld_v8_evict_first(const void* p, uint32_t r[8]) {
    asm volatile("ld.global.nc.L2::evict_first.v8.b32 {%0,%1,%2,%3,%4,%5,%6,%7}, [%8];"
                 : "=r"(r[0]), "=r"(r[1]), "=r"(r[2]), "=r"(r[3]),
                   "=r"(r[4]), "=r"(r[5]), "=r"(r[6]), "=r"(r[7])
                 : "l"(p));
}
__device__ __forceinline__ void st_v8_evict_last(void* p, const uint32_t r[8]) {
    asm volatile("st.global.L2::evict_last.v8.b32 [%0], {%1,%2,%3,%4,%5,%6,%7,%8};"
                 :: "l"(p),
                    "r"(r[0]), "r"(r[1]), "r"(r[2]), "r"(r[3]),
                    "r"(r[4]), "r"(r[5]), "r"(r[6]), "r"(r[7])
                 : "memory");
}

// out[b, 0:64] = full_input[b, idx[b]*64 : idx[b]*64+64]
// slot = one 32 B chunk of the output; 8 slots (8 lanes) per row.
// Warp layout per leg: lanes l cover slots [warp_s0 + l], i.e. 4 consecutive
// rows. Lane l (l < 16) loads the index for row (leg = l/4, row = l%4); all
// lanes receive theirs via __shfl_sync. 16 idx LDGs per warp-iteration
// instead of 128.
__global__ void __launch_bounds__(512)
multiplexer_kernel(const char* __restrict__ full_input,
                   const int* __restrict__ indices,
                   char* __restrict__ out,
                   int total_slots, int stride_slots) {
    const int tid  = blockIdx.x * blockDim.x + threadIdx.x;
    const int lane = threadIdx.x & 31;
    const int warp_s0 = tid & ~31;               // first slot of this warp, leg 0

    int s0 = tid;
    int s1 = s0 + stride_slots;
    int s2 = s1 + stride_slots;
    int s3 = s2 + stride_slots;

    if (s3 < total_slots) {
        // ---- index loads: one per (leg, row-in-warp), lanes 0..15 ----
        // leg L base slot = warp_s0 + L*stride_slots; rows = base>>3 .. base>>3+3
        int my_idx = 0;
        if (lane < 16) {
            int L = lane >> 2;                   // which leg
            int r = lane & 3;                    // which row within the warp
            int row = ((warp_s0 + L * stride_slots) >> 3) + r;
            my_idx = __ldg(&indices[row]);
        }
        // distribute: for leg L, lane l needs row (l>>3) -> source lane L*4 + (l>>3)
        int src = lane >> 3;                     // row-in-warp for this lane
        int i0 = __shfl_sync(0xffffffffu, my_idx, 0 * ROWS_PER_WARP_LEG + src);
        int i1 = __shfl_sync(0xffffffffu, my_idx, 1 * ROWS_PER_WARP_LEG + src);
        int i2 = __shfl_sync(0xffffffffu, my_idx, 2 * ROWS_PER_WARP_LEG + src);
        int i3 = __shfl_sync(0xffffffffu, my_idx, 3 * ROWS_PER_WARP_LEG + src);

        int b0 = s0 >> 3, j0 = s0 & 7;
        int b1 = s1 >> 3, j1 = s1 & 7;
        int b2 = s2 >> 3, j2 = s2 & 7;
        int b3 = s3 >> 3, j3 = s3 & 7;

        uint32_t v0[8], v1[8], v2[8], v3[8];
        ld_v8_evict_first(full_input + (size_t)b0 * FULL_ROW_BYTES + i0 * BLOCK_BYTES + j0 * VEC_BYTES, v0);
        ld_v8_evict_first(full_input + (size_t)b1 * FULL_ROW_BYTES + i1 * BLOCK_BYTES + j1 * VEC_BYTES, v1);
        ld_v8_evict_first(full_input + (size_t)b2 * FULL_ROW_BYTES + i2 * BLOCK_BYTES + j2 * VEC_BYTES, v2);
        ld_v8_evict_first(full_input + (size_t)b3 * FULL_ROW_BYTES + i3 * BLOCK_BYTES + j3 * VEC_BYTES, v3);

        st_v8_evict_last(out + (size_t)s0 * VEC_BYTES, v0);
        st_v8_evict_last(out + (size_t)s1 * VEC_BYTES, v1);
        st_v8_evict_last(out + (size_t)s2 * VEC_BYTES, v2);
        st_v8_evict_last(out + (size_t)s3 * VEC_BYTES, v3);
    } else {
        #pragma unroll
        for (int u = 0; u < UNROLL; u++) {
            int s = s0 + u * stride_slots;
            if (s < total_slots) {
                int b = s >> 3, j = s & 7;
                int i = __ldg(&indices[b]);
                uint32_t v[8];
                ld_v8_evict_first(full_input + (size_t)b * FULL_ROW_BYTES + i * BLOCK_BYTES + j * VEC_BYTES, v);
                st_v8_evict_last(out + (size_t)s * VEC_BYTES, v);
            }
        }
    }
}

extern "C" void kernel_launch(void* const* d_in, const int* in_sizes, int n_in,
                              void* d_out, int out_size) {
    const char* full_input = (const char*)d_in[0];
    const int*  indices    = (const int*)d_in[1];
    char*       out        = (char*)d_out;

    int batch       = in_sizes[1];                  // 262144
    int total_slots = batch * SLOTS_PER_ROW;        // 2,097,152 slots (32 B each)
    int block       = 512;
    int threads     = (total_slots + UNROLL - 1) / UNROLL;  // 524,288
    int grid        = (threads + block - 1) / block;        // 1024
    int stride      = grid * block;                 // 524,288 (stride divisible by 8:
                                                    // every leg keeps lane->slot alignment)

    multiplexer_kernel<<<grid, block>>>(full_input, indices, out, total_slots, stride);
}